// round 2
// baseline (speedup 1.0000x reference)
#include <cuda_runtime.h>
#include <math.h>

// Problem constants
#define NPTS   30000
#define NV     4
#define SNB    6
#define PBLK   8            // points per block
#define RBLK   (PBLK * 7)   // 56 rows (center + 6 neighbors per point)
#define HD     256          // hidden dim (K and output cols of fused GEMM)
#define KT     64           // K-tile staged in shared

// ---- device scratch (allocation-free: static __device__ globals) ----
__device__ float g_M[NV * 256 * 256];   // M[v] = W2[v] @ A1b[v]   (256x256)
__device__ float g_C[NV * 256];         // C[v] = b2[v]@A1b[v] + Ab1[v]

// ---------------- precompute kernels ----------------
__global__ void precompute_M(const float* __restrict__ W2, const float* __restrict__ A1) {
    int v = blockIdx.y, h1 = blockIdx.x, h2 = threadIdx.x;
    __shared__ float w2row[128];
    if (threadIdx.x < 128) w2row[threadIdx.x] = W2[(v * 256 + h1) * 128 + threadIdx.x];
    __syncthreads();
    const float* a1 = A1 + (v * 320) * 256 + h2;   // A1b rows 0..127
    float acc = 0.f;
#pragma unroll 8
    for (int o = 0; o < 128; o++) acc += w2row[o] * a1[o * 256];
    g_M[(v * 256 + h1) * 256 + h2] = acc;
}

__global__ void precompute_C(const float* __restrict__ b2, const float* __restrict__ A1,
                             const float* __restrict__ Ab1) {
    int v = blockIdx.x, h2 = threadIdx.x;
    __shared__ float b2s[128];
    if (threadIdx.x < 128) b2s[threadIdx.x] = b2[v * 128 + threadIdx.x];
    __syncthreads();
    float acc = Ab1[v * 256 + h2];
#pragma unroll 8
    for (int o = 0; o < 128; o++) acc += b2s[o] * A1[(v * 320 + o) * 256 + h2];
    g_C[v * 256 + h2] = acc;
}

// ---------------- packed fp32x2 helpers ----------------
__device__ __forceinline__ unsigned long long pk2(float x, float y) {
    unsigned long long r;
    asm("mov.b64 %0, {%1, %2};" : "=l"(r) : "f"(x), "f"(y));
    return r;
}
__device__ __forceinline__ void unpk2(unsigned long long p, float& x, float& y) {
    asm("mov.b64 {%0, %1}, %2;" : "=f"(x), "=f"(y) : "l"(p));
}
__device__ __forceinline__ void fma2(unsigned long long& d, unsigned long long a, unsigned long long b) {
    asm("fma.rn.f32x2 %0, %1, %2, %0;" : "+l"(d) : "l"(a), "l"(b));
}

// ---------------- shared memory layout (floats) ----------------
// reluT [56][256] : 0      .. 14336
// Msh   [64][256] : 14336  .. 30720
// ep    [8][256]  : 30720  .. 32768
// sN    [8][128]  : 32768  .. 33792
// sG    [8][64]   : 33792  .. 34304
// xf    [56][8]   : 34304  .. 34752
// sInv  [8][6]    : 34752  .. 34800
// sA2   [256]     : 34800  .. 35056
#define SMEM_FLOATS 35056
#define SMEM_BYTES  (SMEM_FLOATS * 4)

// ---------------- main fused kernel ----------------
__global__ void __launch_bounds__(256, 1)
surface_main_kernel(
    const float* __restrict__ centers,   const float* __restrict__ encG,
    const float* __restrict__ encN,      const float* __restrict__ nbrs,
    const float* __restrict__ norms,     const float* __restrict__ nbrnorms,
    const float* __restrict__ areas,     const float* __restrict__ nbrareas,
    const float* __restrict__ W1,        const float* __restrict__ b1,
    const float* __restrict__ A1,        const float* __restrict__ A2,
    const float* __restrict__ Ab2,       float* __restrict__ out)
{
    extern __shared__ float smem[];
    float* reluT = smem;
    float* Msh   = smem + 14336;
    float* ep    = smem + 30720;
    float* sN    = smem + 32768;
    float* sG    = smem + 33792;
    float* xf    = smem + 34304;
    float* sInv  = smem + 34752;
    float* sA2   = smem + 34800;

    const int v   = blockIdx.y;
    const int n0  = blockIdx.x * PBLK;
    const int tid = threadIdx.x;

    // ---- phase 1: stage encodings, features, A2 ----
    for (int i = tid; i < PBLK * 128; i += 256) {
        int p = i >> 7, c = i & 127;
        sN[i] = encN[(n0 + p) * 128 + c];
    }
    for (int i = tid; i < PBLK * 64; i += 256) {
        int p = i >> 6, c = i & 63;
        sG[i] = encG[(n0 + p) * 64 + c];
    }
    sA2[tid] = A2[v * 256 + tid];

    float f[7];
    int p = 0, it = 0;
    if (tid < RBLK) {
        p  = tid / 7;
        it = tid - p * 7;
        int n = n0 + p;
        if (it == 0) {
            f[0] = centers[n * 3 + 0]; f[1] = centers[n * 3 + 1]; f[2] = centers[n * 3 + 2];
            f[3] = norms[n * 3 + 0];   f[4] = norms[n * 3 + 1];   f[5] = norms[n * 3 + 2];
            f[6] = logf(areas[n]) * 0.1f;
        } else {
            int s = it - 1;
            int base = (n * SNB + s) * 3;
            f[0] = nbrs[base + 0] + 1e-6f;     f[1] = nbrs[base + 1] + 1e-6f;     f[2] = nbrs[base + 2] + 1e-6f;
            f[3] = nbrnorms[base + 0] + 1e-6f; f[4] = nbrnorms[base + 1] + 1e-6f; f[5] = nbrnorms[base + 2] + 1e-6f;
            f[6] = logf(nbrareas[n * SNB + s]) * 0.1f + 1e-6f;
        }
#pragma unroll
        for (int i = 0; i < 7; i++) xf[tid * 8 + i] = f[i];
    }
    __syncthreads();

    // inverse distance (needs center row of same point, written by another thread)
    if (tid < RBLK && it != 0) {
        float d2 = 0.f;
#pragma unroll
        for (int i = 0; i < 7; i++) {
            float d = xf[(p * 7) * 8 + i] - f[i];
            d2 += d * d;
        }
        sInv[p * 6 + (it - 1)] = 1.0f / sqrtf(d2);
    }

    // ---- phase 2: relu_T[r][k] = relu(x[r] . W1[v][:,k] + b1[v][k]) ----
    {
        const int k = tid;
        float w[7];
#pragma unroll
        for (int i = 0; i < 7; i++) w[i] = W1[(v * 7 + i) * 256 + k];
        const float bb = b1[v * 256 + k];
        for (int r = 0; r < RBLK; r++) {
            float t = bb;
#pragma unroll
            for (int i = 0; i < 7; i++) t = fmaf(xf[r * 8 + i], w[i], t);
            reluT[r * 256 + k] = fmaxf(t, 0.f);
        }
    }

    // ---- phase 3: enc_pre[p][h] = C[v][h] + encN.A1n + encG.A1g ----
    {
        const int h = tid;
        float acc[PBLK];
        float c0 = g_C[v * 256 + h];
#pragma unroll
        for (int q = 0; q < PBLK; q++) acc[q] = c0;
        const float* a1n = A1 + (v * 320 + 128) * 256 + h;
        for (int i = 0; i < 128; i++) {
            float a = a1n[i * 256];
#pragma unroll
            for (int q = 0; q < PBLK; q++) acc[q] = fmaf(sN[q * 128 + i], a, acc[q]);
        }
        const float* a1g = A1 + (v * 320 + 256) * 256 + h;
        for (int i = 0; i < 64; i++) {
            float a = a1g[i * 256];
#pragma unroll
            for (int q = 0; q < PBLK; q++) acc[q] = fmaf(sG[q * 64 + i], a, acc[q]);
        }
#pragma unroll
        for (int q = 0; q < PBLK; q++) ep[q * 256 + h] = acc[q];
    }
    __syncthreads();

    // ---- phase 4: Z = relu_T @ M[v]  (56x256 @ 256x256), reg tile 7 rows x 8 cols ----
    const int tr = tid >> 5;   // warp id = point index within block
    const int tc = tid & 31;

    unsigned long long acc2[7][4];
#pragma unroll
    for (int j = 0; j < 7; j++)
#pragma unroll
        for (int q = 0; q < 4; q++) acc2[j][q] = 0ull;

    for (int kt = 0; kt < HD / KT; kt++) {
        // stage M k-tile (64x256) into shared
        const float4* src = (const float4*)(g_M + (v * 256 + kt * KT) * 256);
        float4* dst = (float4*)Msh;
#pragma unroll
        for (int q = 0; q < 16; q++) dst[tid + 256 * q] = src[tid + 256 * q];
        __syncthreads();

        for (int kk = 0; kk < KT; kk++) {
            const int k = kt * KT + kk;
            float4 bA = *(const float4*)(Msh + kk * 256 + 4 * tc);
            float4 bB = *(const float4*)(Msh + kk * 256 + 128 + 4 * tc);
            unsigned long long b01 = pk2(bA.x, bA.y);
            unsigned long long b23 = pk2(bA.z, bA.w);
            unsigned long long b45 = pk2(bB.x, bB.y);
            unsigned long long b67 = pk2(bB.z, bB.w);
#pragma unroll
            for (int j = 0; j < 7; j++) {
                float a = reluT[(tr * 7 + j) * 256 + k];
                unsigned long long aa = pk2(a, a);
                fma2(acc2[j][0], aa, b01);
                fma2(acc2[j][1], aa, b23);
                fma2(acc2[j][2], aa, b45);
                fma2(acc2[j][3], aa, b67);
            }
        }
        __syncthreads();
    }

    // ---- epilogue: relu(Z + enc_pre) . A2, warp-reduce, inverse-distance combine ----
    const float Ab2v = Ab2[v];
    float s[7];
#pragma unroll
    for (int j = 0; j < 7; j++) {
        float sum = 0.f;
#pragma unroll
        for (int q = 0; q < 4; q++) {
            int base = ((q >= 2) ? 128 : 0) + 4 * tc + (q & 1) * 2;
            float z0, z1;
            unpk2(acc2[j][q], z0, z1);
            sum += fmaxf(z0 + ep[tr * 256 + base], 0.f) * sA2[base];
            sum += fmaxf(z1 + ep[tr * 256 + base + 1], 0.f) * sA2[base + 1];
        }
#pragma unroll
        for (int o = 16; o > 0; o >>= 1) sum += __shfl_xor_sync(0xffffffffu, sum, o);
        s[j] = sum + Ab2v;
    }

    if ((tid & 31) == 0) {
        float num = 0.f, den = 0.f;
#pragma unroll
        for (int q = 1; q < 7; q++) {
            float iv = sInv[tr * 6 + (q - 1)];
            num += s[q] * iv;
            den += iv;
        }
        out[(n0 + tr) * NV + v] = 0.5f * s[0] + 0.5f * num / den;
    }
}

// ---------------- launch ----------------
extern "C" void kernel_launch(void* const* d_in, const int* in_sizes, int n_in,
                              void* d_out, int out_size) {
    const float* centers  = (const float*)d_in[0];
    const float* encG     = (const float*)d_in[1];
    const float* encN     = (const float*)d_in[2];
    const float* nbrs     = (const float*)d_in[3];
    const float* norms    = (const float*)d_in[4];
    const float* nbrnorms = (const float*)d_in[5];
    const float* areas    = (const float*)d_in[6];
    const float* nbrareas = (const float*)d_in[7];
    // d_in[8], d_in[9]: global_params_* (unused by reference)
    const float* W1  = (const float*)d_in[10];
    const float* b1  = (const float*)d_in[11];
    const float* W2  = (const float*)d_in[12];
    const float* b2  = (const float*)d_in[13];
    const float* A1  = (const float*)d_in[14];
    const float* Ab1 = (const float*)d_in[15];
    const float* A2  = (const float*)d_in[16];
    const float* Ab2 = (const float*)d_in[17];
    float* out = (float*)d_out;

    precompute_M<<<dim3(256, NV), 256>>>(W2, A1);
    precompute_C<<<NV, 256>>>(b2, A1, Ab1);

    cudaFuncSetAttribute(surface_main_kernel,
                         cudaFuncAttributeMaxDynamicSharedMemorySize, SMEM_BYTES);
    surface_main_kernel<<<dim3(NPTS / PBLK, NV), 256, SMEM_BYTES>>>(
        centers, encG, encN, nbrs, norms, nbrnorms, areas, nbrareas,
        W1, b1, A1, A2, Ab2, out);
}

// round 4
// speedup vs baseline: 2.2094x; 2.2094x over previous
#include <cuda_runtime.h>
#include <cuda_fp16.h>
#include <math.h>
#include <stdint.h>

#define NPTS   30000
#define NV     4
#define SNB    6
#define PTILE  16
#define MROWS  128                 // 16 pts * 8 rows (7 items + 1 pad)
#define TILES_MAIN (NPTS / PTILE)  // 1875
#define GRIDX  37
#define EP_ROWS 128
#define EP_TILES ((NPTS + EP_ROWS - 1) / EP_ROWS)  // 235

#define ASTR 264   // main A/B smem row stride in halves (33 * 16B -> conflict-free LDSM)
#define ESTR 200   // ep   A/B smem row stride in halves (25 * 16B)

// ---------------- device scratch (allocation-free) ----------------
__device__ __align__(16) __half g_Mt[NV * 256 * ASTR];    // M^T[v][n][k], padded rows
__device__ __align__(16) __half g_Ang[NV * 256 * ESTR];   // A1ng^T[v][h][i], padded rows
__device__ float    g_C[NV * 256];                         // b2@A1b + Ab1
__device__ uint32_t g_ep[NV * NPTS * 128];                 // enc_pre as half2 pairs

// ---------------- helpers ----------------
__device__ __forceinline__ uint32_t smem_u32(const void* p) {
    uint32_t a;
    asm("{ .reg .u64 t; cvta.to.shared.u64 t, %1; cvt.u32.u64 %0, t; }" : "=r"(a) : "l"(p));
    return a;
}
__device__ __forceinline__ void ldsm_x4(uint32_t r[4], uint32_t addr) {
    asm volatile("ldmatrix.sync.aligned.m8n8.x4.shared.b16 {%0,%1,%2,%3}, [%4];"
                 : "=r"(r[0]), "=r"(r[1]), "=r"(r[2]), "=r"(r[3]) : "r"(addr));
}
__device__ __forceinline__ void ldsm_x2(uint32_t& r0, uint32_t& r1, uint32_t addr) {
    asm volatile("ldmatrix.sync.aligned.m8n8.x2.shared.b16 {%0,%1}, [%2];"
                 : "=r"(r0), "=r"(r1) : "r"(addr));
}
__device__ __forceinline__ void mma_16816(float c[4], const uint32_t a[4],
                                          uint32_t b0, uint32_t b1) {
    asm volatile("mma.sync.aligned.m16n8k16.row.col.f32.f16.f16.f32 "
                 "{%0,%1,%2,%3}, {%4,%5,%6,%7}, {%8,%9}, {%0,%1,%2,%3};"
                 : "+f"(c[0]), "+f"(c[1]), "+f"(c[2]), "+f"(c[3])
                 : "r"(a[0]), "r"(a[1]), "r"(a[2]), "r"(a[3]), "r"(b0), "r"(b1));
}
// packed f32x2
__device__ __forceinline__ unsigned long long pk2(float x, float y) {
    unsigned long long r; asm("mov.b64 %0, {%1, %2};" : "=l"(r) : "f"(x), "f"(y)); return r;
}
__device__ __forceinline__ void unpk2(unsigned long long p, float& x, float& y) {
    asm("mov.b64 {%0, %1}, %2;" : "=f"(x), "=f"(y) : "l"(p));
}
__device__ __forceinline__ void fma2(unsigned long long& d, unsigned long long a, unsigned long long b) {
    asm("fma.rn.f32x2 %0, %1, %2, %0;" : "+l"(d) : "l"(a), "l"(b));
}
__device__ __forceinline__ uint32_t f22u(float a, float b) {
    __half2 h = __floats2half2_rn(a, b);
    return *reinterpret_cast<uint32_t*>(&h);
}

// ---------------- precompute kernels ----------------
__global__ void precompute_Mt(const float* __restrict__ W2, const float* __restrict__ A1) {
    int v = blockIdx.y, k = blockIdx.x, n = threadIdx.x;   // M[k][n] = sum_o W2[k][o]*A1b[o][n]
    __shared__ float w2row[128];
    if (threadIdx.x < 128) w2row[threadIdx.x] = W2[(v * 256 + k) * 128 + threadIdx.x];
    __syncthreads();
    const float* a1 = A1 + (v * 320) * 256 + n;
    float acc = 0.f;
#pragma unroll 8
    for (int o = 0; o < 128; o++) acc += w2row[o] * a1[o * 256];
    g_Mt[v * 256 * ASTR + n * ASTR + k] = __float2half(acc);
}

__global__ void precompute_C(const float* __restrict__ b2, const float* __restrict__ A1,
                             const float* __restrict__ Ab1) {
    int v = blockIdx.x, h = threadIdx.x;
    __shared__ float b2s[128];
    if (threadIdx.x < 128) b2s[threadIdx.x] = b2[v * 128 + threadIdx.x];
    __syncthreads();
    float acc = Ab1[v * 256 + h];
#pragma unroll 8
    for (int o = 0; o < 128; o++) acc += b2s[o] * A1[(v * 320 + o) * 256 + h];
    g_C[v * 256 + h] = acc;
}

__global__ void precompute_Ang(const float* __restrict__ A1) {
    int b = blockIdx.x;            // NV*192 blocks
    int v = b / 192, i = b % 192, h = threadIdx.x;
    g_Ang[v * 256 * ESTR + h * ESTR + i] = __float2half(A1[(v * 320 + 128 + i) * 256 + h]);
}

// ---------------- ep prepass: ep[v][n][h] = ENC[n]@A1ng[v] + C[v] (fp16) ----------------
// smem: B [256][200]h = 102400 | A [128][200]h = 51200 | C 1024
#define E_B 0
#define E_A 102400
#define E_C 153600
#define EP_SMEM 154624

__global__ void __launch_bounds__(512, 1)
ep_kernel(const float* __restrict__ encN, const float* __restrict__ encG) {
    extern __shared__ unsigned char smem[];
    const uint32_t sb = smem_u32(smem);
    const int tid = threadIdx.x, wid = tid >> 5, lane = tid & 31;
    const int v = blockIdx.y;
    const int wm = wid & 3, wn = wid >> 2;

    { // B = A1ng^T copy (padded rows)
        const float4* src = (const float4*)(g_Ang + v * 256 * ESTR);
        float4* dst = (float4*)(smem + E_B);
        for (int i = tid; i < 6400; i += 512) dst[i] = src[i];
    }
    float* sC = (float*)(smem + E_C);
    for (int i = tid; i < 256; i += 512) sC[i] = g_C[v * 256 + i];
    __syncthreads();

    uint32_t aBase[2], bBase;
#pragma unroll
    for (int mt = 0; mt < 2; mt++)
        aBase[mt] = sb + E_A + (uint32_t)(((wm * 32 + mt * 16 + (lane & 15)) * ESTR
                                          + ((lane >> 4) * 8)) * 2);
    bBase = sb + E_B + (uint32_t)(((wn * 64 + (lane & 7)) * ESTR
                                   + (((lane >> 3) & 1) * 8)) * 2);
    const int l4 = lane >> 2, l2 = (lane & 3) * 2;

    for (int t = blockIdx.x; t < EP_TILES; t += GRIDX) {
        const int n0 = t * EP_ROWS;
        // A: enc rows fp32 -> fp16 (K=192, zero-padded rows beyond NPTS)
        for (int idx = tid; idx < 128 * 96; idx += 512) {
            int r = idx / 96, kk = (idx % 96) * 2;
            int n = n0 + r;
            float e0 = 0.f, e1 = 0.f;
            if (n < NPTS) {
                if (kk < 128) { e0 = encN[n * 128 + kk];      e1 = encN[n * 128 + kk + 1]; }
                else          { e0 = encG[n * 64 + kk - 128]; e1 = encG[n * 64 + kk - 127]; }
            }
            *(uint32_t*)(smem + E_A + (r * ESTR + kk) * 2) = f22u(e0, e1);
        }
        __syncthreads();

        float acc[2][8][4];
#pragma unroll
        for (int mt = 0; mt < 2; mt++)
#pragma unroll
            for (int nt = 0; nt < 8; nt++)
#pragma unroll
                for (int q = 0; q < 4; q++) acc[mt][nt][q] = 0.f;

#pragma unroll 4
        for (int ks = 0; ks < 12; ks++) {
            uint32_t a0[4], a1[4];
            ldsm_x4(a0, aBase[0] + ks * 32);
            ldsm_x4(a1, aBase[1] + ks * 32);
#pragma unroll
            for (int nt = 0; nt < 8; nt++) {
                uint32_t b0, b1;
                ldsm_x2(b0, b1, bBase + nt * (8 * ESTR * 2) + ks * 32);
                mma_16816(acc[0][nt], a0, b0, b1);
                mma_16816(acc[1][nt], a1, b0, b1);
            }
        }

        // write g_ep (+C), fp16 pairs
#pragma unroll
        for (int mt = 0; mt < 2; mt++)
#pragma unroll
            for (int x = 0; x < 2; x++) {
                int row = wm * 32 + mt * 16 + x * 8 + l4;
                int n = n0 + row;
                if (n < NPTS) {
                    uint32_t* dst = &g_ep[(v * NPTS + n) * 128];
#pragma unroll
                    for (int nt = 0; nt < 8; nt++) {
                        int col = wn * 64 + nt * 8 + l2;
                        dst[col >> 1] = f22u(acc[mt][nt][2 * x] + sC[col],
                                             acc[mt][nt][2 * x + 1] + sC[col + 1]);
                    }
                }
            }
        __syncthreads();
    }
}

// ---------------- main fused kernel ----------------
// smem (bytes):
// B (Mt)  [256][264]h : 0      .. 135168
// A (R)   [128][264]h : 135168 .. 202752
// ep      [128][64]u32: 202752 .. 210944
// W1      [7][256]f   : 210944 .. 218112
// b1      [256]f      : 218112 .. 219136
// A2      [256]f      : 219136 .. 220160
// xf      [128][8]f   : 220160 .. 224256
// inv     [16][6]f    : 224256 .. 224640
// row     [128][4]f   : 224640 .. 226688
// ss      [128]f      : 226688 .. 227200
#define M_B   0
#define M_A   135168
#define M_EP  202752
#define M_W1  210944
#define M_B1  218112
#define M_A2  219136
#define M_XF  220160
#define M_INV 224256
#define M_ROW 224640
#define M_SS  226688
#define MAIN_SMEM 227200

__global__ void __launch_bounds__(512, 1)
main_kernel(const float* __restrict__ centers,  const float* __restrict__ nbrs,
            const float* __restrict__ norms,    const float* __restrict__ nbrnorms,
            const float* __restrict__ areas,    const float* __restrict__ nbrareas,
            const float* __restrict__ W1,       const float* __restrict__ b1,
            const float* __restrict__ A2,       const float* __restrict__ Ab2,
            float* __restrict__ out) {
    extern __shared__ unsigned char smem[];
    const uint32_t sb = smem_u32(smem);
    const int tid = threadIdx.x, wid = tid >> 5, lane = tid & 31;
    const int v = blockIdx.y;
    const int wm = wid & 3, wn = wid >> 2;

    float*    sW1  = (float*)(smem + M_W1);
    float*    sB1  = (float*)(smem + M_B1);
    float*    sA2  = (float*)(smem + M_A2);
    float*    sXF  = (float*)(smem + M_XF);
    float*    sInv = (float*)(smem + M_INV);
    float*    sRow = (float*)(smem + M_ROW);
    float*    sS   = (float*)(smem + M_SS);
    uint32_t* sEP  = (uint32_t*)(smem + M_EP);

    { // resident B = M^T (135 KB)
        const float4* src = (const float4*)(g_Mt + v * 256 * ASTR);
        float4* dst = (float4*)(smem + M_B);
        for (int i = tid; i < 8448; i += 512) dst[i] = src[i];
    }
    for (int i = tid; i < 256; i += 512) { sA2[i] = A2[v * 256 + i]; sB1[i] = b1[v * 256 + i]; }
    for (int i = tid; i < 7 * 256; i += 512) sW1[i] = W1[v * 7 * 256 + i];
    const float Ab2v = Ab2[v];
    __syncthreads();

    uint32_t aBase[2], bBase;
#pragma unroll
    for (int mt = 0; mt < 2; mt++)
        aBase[mt] = sb + M_A + (uint32_t)(((wm * 32 + mt * 16 + (lane & 15)) * ASTR
                                          + ((lane >> 4) * 8)) * 2);
    bBase = sb + M_B + (uint32_t)(((wn * 64 + (lane & 7)) * ASTR
                                   + (((lane >> 3) & 1) * 8)) * 2);
    const int l4 = lane >> 2, l2 = (lane & 3) * 2;

    for (int t = blockIdx.x; t < TILES_MAIN; t += GRIDX) {
        const int n0 = t * PTILE;

        // ---- stage features + ep ----
        if (tid < MROWS) {
            const int p = tid >> 3, i = tid & 7, n = n0 + p;
            float f[7];
            if (i == 0) {
                f[0] = centers[n * 3 + 0]; f[1] = centers[n * 3 + 1]; f[2] = centers[n * 3 + 2];
                f[3] = norms[n * 3 + 0];   f[4] = norms[n * 3 + 1];   f[5] = norms[n * 3 + 2];
                f[6] = logf(areas[n]) * 0.1f;
            } else if (i < 7) {
                int s = i - 1, base = (n * SNB + s) * 3;
                f[0] = nbrs[base + 0] + 1e-6f;     f[1] = nbrs[base + 1] + 1e-6f;     f[2] = nbrs[base + 2] + 1e-6f;
                f[3] = nbrnorms[base + 0] + 1e-6f; f[4] = nbrnorms[base + 1] + 1e-6f; f[5] = nbrnorms[base + 2] + 1e-6f;
                f[6] = logf(nbrareas[n * SNB + s]) * 0.1f + 1e-6f;
            } else {
#pragma unroll
                for (int j = 0; j < 7; j++) f[j] = 0.f;
            }
#pragma unroll
            for (int j = 0; j < 7; j++) sXF[tid * 8 + j] = f[j];
            sXF[tid * 8 + 7] = 0.f;
        }
        {
            const int base = (v * NPTS + n0) * 128;
            for (int i = tid; i < 2048; i += 512) sEP[i] = g_ep[base + i];
        }
        __syncthreads();

        // inverse distance
        if (tid < MROWS) {
            const int p = tid >> 3, i = tid & 7;
            if (i >= 1 && i < 7) {
                float d2 = 0.f;
#pragma unroll
                for (int j = 0; j < 7; j++) {
                    float d = sXF[(p * 8) * 8 + j] - sXF[tid * 8 + j];
                    d2 += d * d;
                }
                sInv[p * 6 + (i - 1)] = rsqrtf(d2);
            }
        }

        // ---- A = relu(x @ W1 + b1) -> fp16 padded smem ----
        {
            const int r = tid >> 2, q = tid & 3;
            unsigned long long xp[7];
#pragma unroll
            for (int j = 0; j < 7; j++) { float x = sXF[r * 8 + j]; xp[j] = pk2(x, x); }
            const int kbase = q * 64;
#pragma unroll
            for (int half = 0; half < 2; half++) {
                unsigned long long acc[16];
                const int k0 = kbase + half * 32;
#pragma unroll
                for (int m = 0; m < 16; m++)
                    acc[m] = *(const unsigned long long*)(sB1 + k0 + m * 2);
#pragma unroll
                for (int j = 0; j < 7; j++) {
                    const unsigned long long* wp = (const unsigned long long*)(sW1 + j * 256 + k0);
#pragma unroll
                    for (int m = 0; m < 16; m++) fma2(acc[m], xp[j], wp[m]);
                }
#pragma unroll
                for (int m = 0; m < 16; m++) {
                    float a, b; unpk2(acc[m], a, b);
                    *(uint32_t*)(smem + M_A + (r * ASTR + k0 + m * 2) * 2) =
                        f22u(fmaxf(a, 0.f), fmaxf(b, 0.f));
                }
            }
        }
        __syncthreads();

        // ---- Z = A @ M^T : 128x256x256, warp tile 32x64, mma.m16n8k16 ----
        float acc[2][8][4];
#pragma unroll
        for (int mt = 0; mt < 2; mt++)
#pragma unroll
            for (int nt = 0; nt < 8; nt++)
#pragma unroll
                for (int q = 0; q < 4; q++) acc[mt][nt][q] = 0.f;

#pragma unroll 4
        for (int ks = 0; ks < 16; ks++) {
            uint32_t a0[4], a1[4];
            ldsm_x4(a0, aBase[0] + ks * 32);
            ldsm_x4(a1, aBase[1] + ks * 32);
#pragma unroll
            for (int nt = 0; nt < 8; nt++) {
                uint32_t b0, b1;
                ldsm_x2(b0, b1, bBase + nt * (8 * ASTR * 2) + ks * 32);
                mma_16816(acc[0][nt], a0, b0, b1);
                mma_16816(acc[1][nt], a1, b0, b1);
            }
        }

        // ---- epilogue: relu(Z + ep) . A2, reduce, inverse-distance combine ----
#pragma unroll
        for (int mt = 0; mt < 2; mt++)
#pragma unroll
            for (int x = 0; x < 2; x++) {
                int row = wm * 32 + mt * 16 + x * 8 + l4;
                int p = row >> 3;
                float s = 0.f;
#pragma unroll
                for (int nt = 0; nt < 8; nt++) {
                    int col = wn * 64 + nt * 8 + l2;
                    __half2 ev = *(__half2*)&sEP[p * 128 + (col >> 1)];
                    float z0 = acc[mt][nt][2 * x]     + __low2float(ev);
                    float z1 = acc[mt][nt][2 * x + 1] + __high2float(ev);
                    s = fmaf(fmaxf(z0, 0.f), sA2[col], s);
                    s = fmaf(fmaxf(z1, 0.f), sA2[col + 1], s);
                }
                s += __shfl_xor_sync(0xffffffffu, s, 1);
                s += __shfl_xor_sync(0xffffffffu, s, 2);
                if ((lane & 3) == 0) sRow[row * 4 + wn] = s;
            }
        __syncthreads();
        if (tid < MROWS)
            sS[tid] = sRow[tid * 4] + sRow[tid * 4 + 1] + sRow[tid * 4 + 2] + sRow[tid * 4 + 3] + Ab2v;
        __syncthreads();
        if (tid < PTILE) {
            float num = 0.f, den = 0.f;
#pragma unroll
            for (int j = 0; j < 6; j++) {
                float iv = sInv[tid * 6 + j];
                num = fmaf(sS[tid * 8 + 1 + j], iv, num);
                den += iv;
            }
            out[(n0 + tid) * NV + v] = 0.5f * sS[tid * 8] + 0.5f * num / den;
        }
        __syncthreads();
    }
}

// ---------------- launch ----------------
extern "C" void kernel_launch(void* const* d_in, const int* in_sizes, int n_in,
                              void* d_out, int out_size) {
    const float* centers  = (const float*)d_in[0];
    const float* encG     = (const float*)d_in[1];
    const float* encN     = (const float*)d_in[2];
    const float* nbrs     = (const float*)d_in[3];
    const float* norms    = (const float*)d_in[4];
    const float* nbrnorms = (const float*)d_in[5];
    const float* areas    = (const float*)d_in[6];
    const float* nbrareas = (const float*)d_in[7];
    const float* W1  = (const float*)d_in[10];
    const float* b1  = (const float*)d_in[11];
    const float* W2  = (const float*)d_in[12];
    const float* b2  = (const float*)d_in[13];
    const float* A1  = (const float*)d_in[14];
    const float* Ab1 = (const float*)d_in[15];
    const float* A2  = (const float*)d_in[16];
    const float* Ab2 = (const float*)d_in[17];
    float* out = (float*)d_out;

    cudaFuncSetAttribute(ep_kernel,   cudaFuncAttributeMaxDynamicSharedMemorySize, EP_SMEM);
    cudaFuncSetAttribute(main_kernel, cudaFuncAttributeMaxDynamicSharedMemorySize, MAIN_SMEM);

    precompute_Mt<<<dim3(256, NV), 256>>>(W2, A1);
    precompute_C<<<NV, 256>>>(b2, A1, Ab1);
    precompute_Ang<<<NV * 192, 256>>>(A1);
    ep_kernel<<<dim3(GRIDX, NV), 512, EP_SMEM>>>(encN, encG);
    main_kernel<<<dim3(GRIDX, NV), 512, MAIN_SMEM>>>(
        centers, nbrs, norms, nbrnorms, areas, nbrareas,
        W1, b1, A2, Ab2, out);
}